// round 1
// baseline (speedup 1.0000x reference)
#include <cuda_runtime.h>
#include <cuda_bf16.h>

#define IMG_H 512
#define IMG_W 512
#define N_IMG 256

__device__ __forceinline__ int mirror_idx(int idx, int n) {
    const int p = 2 * (n - 1);
    int i = abs(idx) % p;
    return (i >= n) ? (p - i) : i;
}

// One CTA per (row y, image b). 128 threads:
//  - stage the two source rows (mirrored row indices) into smem, coalesced float4
//  - each thread computes 4 consecutive output pixels, writes one float4
__global__ __launch_bounds__(128, 16)
void shift_bilinear_kernel(const float* __restrict__ images,
                           const float* __restrict__ dxdy,
                           float* __restrict__ out) {
    __shared__ float s0[IMG_W];
    __shared__ float s1[IMG_W];

    const int y = blockIdx.x;
    const int b = blockIdx.y;
    const int t = threadIdx.x;

    const float dy = dxdy[2 * b + 0];
    const float dx = dxdy[2 * b + 1];

    // Row coordinates — computed exactly like the reference (cy = y - dy)
    const float cy  = (float)y - dy;
    const float y0f = floorf(cy);
    const float fy  = cy - y0f;
    const int   y0  = (int)y0f;
    const int   r0  = mirror_idx(y0,     IMG_H);
    const int   r1  = mirror_idx(y0 + 1, IMG_H);

    const float* img = images + (size_t)b * IMG_H * IMG_W;
    const float4* row0 = (const float4*)(img + (size_t)r0 * IMG_W);
    const float4* row1 = (const float4*)(img + (size_t)r1 * IMG_W);

    // 512 floats = 128 float4 per row; 1 float4 per thread per row
    ((float4*)s0)[t] = row0[t];
    ((float4*)s1)[t] = row1[t];
    __syncthreads();

    const int xbase = t * 4;
    float4 res;
    float* resf = (float*)&res;

#pragma unroll
    for (int j = 0; j < 4; j++) {
        const int   x   = xbase + j;
        const float cx  = (float)x - dx;
        const float x0f = floorf(cx);
        const float fx  = cx - x0f;
        const int   x0  = (int)x0f;
        const int   xm0 = mirror_idx(x0,     IMG_W);
        const int   xm1 = mirror_idx(x0 + 1, IMG_W);

        const float v00 = s0[xm0];
        const float v01 = s0[xm1];
        const float v10 = s1[xm0];
        const float v11 = s1[xm1];

        const float top = (1.0f - fx) * v00 + fx * v01;
        const float bot = (1.0f - fx) * v10 + fx * v11;
        resf[j] = (1.0f - fy) * top + fy * bot;
    }

    float* orow = out + ((size_t)b * IMG_H + y) * IMG_W;
    ((float4*)orow)[t] = res;
}

extern "C" void kernel_launch(void* const* d_in, const int* in_sizes, int n_in,
                              void* d_out, int out_size) {
    const float* images = (const float*)d_in[0];  // (256, 512, 512, 1) f32
    const float* dxdy   = (const float*)d_in[1];  // (256, 2) f32
    float* out = (float*)d_out;                   // (256, 512, 512) f32

    dim3 grid(IMG_H, N_IMG);   // x = row, y = image (consecutive blocks share rows -> L2 reuse)
    dim3 block(128);
    shift_bilinear_kernel<<<grid, block>>>(images, dxdy, out);
}

// round 2
// speedup vs baseline: 1.0085x; 1.0085x over previous
#include <cuda_runtime.h>
#include <cuda_bf16.h>

#define IMG_H 512
#define IMG_W 512
#define N_IMG 256

__device__ __forceinline__ int mirror_idx(int idx, int n) {
    const int p = 2 * (n - 1);
    int i = abs(idx) % p;
    return (i >= n) ? (p - i) : i;
}

// One CTA per (row y, image b). 128 threads.
// Pass 1: load the two mirrored source rows (coalesced float4), blend
//         vertically in registers, store ONE blended row to smem.
// Pass 2: each thread produces 4 output pixels. Interior fast path:
//         two aligned conflict-free LDS.128 + 5-float select. Edge threads
//         take a scalar mirrored slow path.
__global__ __launch_bounds__(128, 16)
void shift_bilinear_kernel(const float* __restrict__ images,
                           const float* __restrict__ dxdy,
                           float* __restrict__ out) {
    __shared__ float4 sb[IMG_W / 4];   // blended row, 512 floats

    const int y = blockIdx.x;
    const int b = blockIdx.y;
    const int t = threadIdx.x;

    const float dy = dxdy[2 * b + 0];
    const float dx = dxdy[2 * b + 1];

    // ---- vertical: mirrored rows + blend ----
    const float cy  = (float)y - dy;
    const float y0f = floorf(cy);
    const float fy  = cy - y0f;
    const int   y0  = (int)y0f;
    const int   r0  = mirror_idx(y0,     IMG_H);
    const int   r1  = mirror_idx(y0 + 1, IMG_H);

    const float* img = images + (size_t)b * IMG_H * IMG_W;
    const float4 a = ((const float4*)(img + (size_t)r0 * IMG_W))[t];
    const float4 c = ((const float4*)(img + (size_t)r1 * IMG_W))[t];

    const float wy0 = 1.0f - fy;
    float4 br;
    br.x = wy0 * a.x + fy * c.x;
    br.y = wy0 * a.y + fy * c.y;
    br.z = wy0 * a.z + fy * c.z;
    br.w = wy0 * a.w + fy * c.w;
    sb[t] = br;
    __syncthreads();

    // ---- horizontal ----
    const int   xb   = 4 * t;
    const float cx0  = (float)xb - dx;
    const int   base = (int)floorf(cx0);   // x0 for pixel j is base + j (interior)
    const int   q0   = base >> 2;          // arithmetic shift = floor div 4

    float4 res;

    if (q0 >= 0 && q0 <= (IMG_W / 4 - 2)) {
        // fast path: columns [base, base+4] all within [0, 511]
        const float4 A = sb[q0];
        const float4 B = sb[q0 + 1];
        float b0, b1, b2, b3, b4;
        switch (base & 3) {
            case 0:  b0 = A.x; b1 = A.y; b2 = A.z; b3 = A.w; b4 = B.x; break;
            case 1:  b0 = A.y; b1 = A.z; b2 = A.w; b3 = B.x; b4 = B.y; break;
            case 2:  b0 = A.z; b1 = A.w; b2 = B.x; b3 = B.y; b4 = B.z; break;
            default: b0 = A.w; b1 = B.x; b2 = B.y; b3 = B.z; b4 = B.w; break;
        }
        const float fx0 = ((float)(xb + 0) - dx) - (float)(base + 0);
        const float fx1 = ((float)(xb + 1) - dx) - (float)(base + 1);
        const float fx2 = ((float)(xb + 2) - dx) - (float)(base + 2);
        const float fx3 = ((float)(xb + 3) - dx) - (float)(base + 3);
        res.x = (1.0f - fx0) * b0 + fx0 * b1;
        res.y = (1.0f - fx1) * b1 + fx1 * b2;
        res.z = (1.0f - fx2) * b2 + fx2 * b3;
        res.w = (1.0f - fx3) * b3 + fx3 * b4;
    } else {
        // slow path: full mirror per pixel
        const float* sbf = (const float*)sb;
        float r[4];
#pragma unroll
        for (int j = 0; j < 4; j++) {
            const float cx  = (float)(xb + j) - dx;
            const float x0f = floorf(cx);
            const float fx  = cx - x0f;
            const int   x0  = (int)x0f;
            const int   xm0 = mirror_idx(x0,     IMG_W);
            const int   xm1 = mirror_idx(x0 + 1, IMG_W);
            r[j] = (1.0f - fx) * sbf[xm0] + fx * sbf[xm1];
        }
        res.x = r[0]; res.y = r[1]; res.z = r[2]; res.w = r[3];
    }

    float* orow = out + ((size_t)b * IMG_H + y) * IMG_W;
    ((float4*)orow)[t] = res;
}

extern "C" void kernel_launch(void* const* d_in, const int* in_sizes, int n_in,
                              void* d_out, int out_size) {
    const float* images = (const float*)d_in[0];  // (256, 512, 512, 1) f32
    const float* dxdy   = (const float*)d_in[1];  // (256, 2) f32
    float* out = (float*)d_out;                   // (256, 512, 512) f32

    dim3 grid(IMG_H, N_IMG);   // consecutive blocks = consecutive rows -> L2 row reuse
    dim3 block(128);
    shift_bilinear_kernel<<<grid, block>>>(images, dxdy, out);
}

// round 3
// speedup vs baseline: 1.5650x; 1.5519x over previous
#include <cuda_runtime.h>
#include <cuda_bf16.h>

#define IMG_H 512
#define IMG_W 512
#define N_IMG 256
#define CHUNK 16   // rows per CTA

__device__ __forceinline__ int mirror_idx(int idx, int n) {
    const int p = 2 * (n - 1);
    int i = abs(idx) % p;
    return (i >= n) ? (p - i) : i;
}

// One CTA per (16-row chunk, image). 128 threads.
// Per-image constants (sy, sx, fy, fx) hoisted: floor(y - dy) = y + floor(-dy).
// Vertical: r1(y) == r0(y+1) exactly -> one new global row load per output row.
// Blend vertically in registers, stage blended row in double-buffered smem
// (one barrier per row), horizontal pass via two aligned conflict-free LDS.128.
__global__ __launch_bounds__(128, 8)
void shift_bilinear_kernel(const float* __restrict__ images,
                           const float* __restrict__ dxdy,
                           float* __restrict__ out) {
    __shared__ float4 sb[2][IMG_W / 4];

    const int t  = threadIdx.x;
    const int b  = blockIdx.y;
    const int y0 = blockIdx.x * CHUNK;

    const float dy = dxdy[2 * b + 0];
    const float dx = dxdy[2 * b + 1];

    // per-image constants
    const float hy  = -dy;
    const float hx  = -dx;
    const float syf = floorf(hy);
    const float sxf = floorf(hx);
    const float fy  = hy - syf;          // constant vertical weight
    const float fx  = hx - sxf;          // constant horizontal weight
    const float wy0 = 1.0f - fy;
    const float wx0 = 1.0f - fx;
    const int   sy  = (int)syf;
    const int   sx  = (int)sxf;

    const float* img  = images + (size_t)b * IMG_H * IMG_W;
    float*       orow = out + ((size_t)b * IMG_H + y0) * IMG_W;

    // horizontal constants
    const int  xb   = 4 * t;
    const int  base = xb + sx;           // x0 for pixel j is base + j
    const int  q0   = base >> 2;
    const int  sel  = sx & 3;            // uniform across CTA & rows
    const bool fast = (q0 >= 0) && (q0 <= (IMG_W / 4 - 2));

    // preload r0 of the first row in the chunk
    float4 rA = ((const float4*)(img + (size_t)mirror_idx(y0 + sy, IMG_H) * IMG_W))[t];

    int y = y0;
#pragma unroll 4
    for (int i = 0; i < CHUNK; ++i, ++y) {
        // r1(y) — becomes r0(y+1) next iteration
        const int r1 = mirror_idx(y + sy + 1, IMG_H);
        const float4 rB = ((const float4*)(img + (size_t)r1 * IMG_W))[t];

        // vertical blend -> smem (double buffered)
        float4 br;
        br.x = wy0 * rA.x + fy * rB.x;
        br.y = wy0 * rA.y + fy * rB.y;
        br.z = wy0 * rA.z + fy * rB.z;
        br.w = wy0 * rA.w + fy * rB.w;
        const int p = i & 1;
        sb[p][t] = br;
        __syncthreads();

        float4 res;
        if (fast) {
            const float4 A = sb[p][q0];
            const float4 B = sb[p][q0 + 1];
            float b0, b1, b2, b3, b4;
            switch (sel) {  // uniform branch
                case 0:  b0 = A.x; b1 = A.y; b2 = A.z; b3 = A.w; b4 = B.x; break;
                case 1:  b0 = A.y; b1 = A.z; b2 = A.w; b3 = B.x; b4 = B.y; break;
                case 2:  b0 = A.z; b1 = A.w; b2 = B.x; b3 = B.y; b4 = B.z; break;
                default: b0 = A.w; b1 = B.x; b2 = B.y; b3 = B.z; b4 = B.w; break;
            }
            res.x = wx0 * b0 + fx * b1;
            res.y = wx0 * b1 + fx * b2;
            res.z = wx0 * b2 + fx * b3;
            res.w = wx0 * b3 + fx * b4;
        } else {
            const float* sbf = (const float*)sb[p];
            float r[4];
#pragma unroll
            for (int j = 0; j < 4; j++) {
                const int x0  = base + j;
                const int xm0 = mirror_idx(x0,     IMG_W);
                const int xm1 = mirror_idx(x0 + 1, IMG_W);
                r[j] = wx0 * sbf[xm0] + fx * sbf[xm1];
            }
            res.x = r[0]; res.y = r[1]; res.z = r[2]; res.w = r[3];
        }

        ((float4*)orow)[t] = res;
        orow += IMG_W;
        rA = rB;
    }
}

extern "C" void kernel_launch(void* const* d_in, const int* in_sizes, int n_in,
                              void* d_out, int out_size) {
    const float* images = (const float*)d_in[0];  // (256, 512, 512, 1) f32
    const float* dxdy   = (const float*)d_in[1];  // (256, 2) f32
    float* out = (float*)d_out;                   // (256, 512, 512) f32

    dim3 grid(IMG_H / CHUNK, N_IMG);
    dim3 block(128);
    shift_bilinear_kernel<<<grid, block>>>(images, dxdy, out);
}

// round 6
// speedup vs baseline: 1.7215x; 1.1000x over previous
#include <cuda_runtime.h>
#include <cuda_bf16.h>

#define IMG_H 512
#define IMG_W 512
#define N_IMG 256
#define WCHUNK 16                 // rows per warp
#define WARPS  4                  // warps per CTA
#define ROWS_PER_CTA (WCHUNK * WARPS)
#define W4 (IMG_W / 4)            // 128 float4 per row

__device__ __forceinline__ int mirror_idx(int idx, int n) {
    const int p = 2 * (n - 1);
    int i = abs(idx) % p;
    return (i >= n) ? (p - i) : i;
}

// Warp-autonomous: each warp owns a 16-row strip + private smem row buffer.
// Per row: 4 prefetched LDG.128/thread (MLP=4), vertical blend in regs,
// STS, __syncwarp, horizontal pass via conflict-free LDS.128, STG.128.
// Row reuse: rA(y) == rB(y-1) exactly -> 1 global row read per output row.
__global__ __launch_bounds__(128, 8)
void shift_bilinear_kernel(const float* __restrict__ images,
                           const float* __restrict__ dxdy,
                           float* __restrict__ out) {
    __shared__ float4 sb[WARPS][2][W4];

    const int t = threadIdx.x & 31;
    const int w = threadIdx.x >> 5;
    const int b = blockIdx.y;
    const int y0 = blockIdx.x * ROWS_PER_CTA + w * WCHUNK;

    const float dy = __ldg(&dxdy[2 * b + 0]);
    const float dx = __ldg(&dxdy[2 * b + 1]);

    // per-image constants: floor(y - dy) = y + floor(-dy)
    const float syf = floorf(-dy);
    const float sxf = floorf(-dx);
    const float fy  = (-dy) - syf;
    const float fx  = (-dx) - sxf;
    const float wy0 = 1.0f - fy;
    const float wx0 = 1.0f - fx;
    const int   sy  = (int)syf;
    const int   sx  = (int)sxf;
    const int   kk  = sx >> 2;     // uniform float4-index shift
    const int   sel = sx & 3;      // uniform sub-word select

    const float4* imgv = (const float4*)(images + (size_t)b * IMG_H * IMG_W);
    float4*       outv = (float4*)(out + (size_t)b * IMG_H * IMG_W);

    // preload rA (src row for y0) and rB (next), lane t holds chunks c*32+t
    float4 rA[4], rB[4], rC[4];
    {
        const size_t ra = (size_t)mirror_idx(y0 + sy,     IMG_H) * W4;
        const size_t rb = (size_t)mirror_idx(y0 + sy + 1, IMG_H) * W4;
#pragma unroll
        for (int c = 0; c < 4; c++) rA[c] = imgv[ra + c * 32 + t];
#pragma unroll
        for (int c = 0; c < 4; c++) rB[c] = imgv[rb + c * 32 + t];
    }

    for (int i = 0; i < WCHUNK; ++i) {
        const int y = y0 + i;

        // prefetch next source row (consumed next iteration) — 4 back-to-back LDG.128
        if (i + 1 < WCHUNK) {
            const size_t rc = (size_t)mirror_idx(y + sy + 2, IMG_H) * W4;
#pragma unroll
            for (int c = 0; c < 4; c++) rC[c] = imgv[rc + c * 32 + t];
        }

        // vertical blend -> private smem buffer (double buffered)
        float4* S = sb[w][i & 1];
#pragma unroll
        for (int c = 0; c < 4; c++) {
            float4 br;
            br.x = wy0 * rA[c].x + fy * rB[c].x;
            br.y = wy0 * rA[c].y + fy * rB[c].y;
            br.z = wy0 * rA[c].z + fy * rB[c].z;
            br.w = wy0 * rA[c].w + fy * rB[c].w;
            S[c * 32 + t] = br;
        }
        __syncwarp();   // STS -> LDS visibility within the warp

        // horizontal pass: output float4 j = c*32+t needs blended float4s j+kk, j+kk+1
        float4* orow = outv + (size_t)y * W4;
#pragma unroll
        for (int c = 0; c < 4; c++) {
            const int j  = c * 32 + t;
            const int q0 = j + kk;
            float4 res;
            if (q0 >= 0 && q0 <= (W4 - 2)) {
                const float4 A = S[q0];
                const float4 B = S[q0 + 1];
                float b0, b1, b2, b3, b4;
                switch (sel) {  // uniform across warp
                    case 0:  b0 = A.x; b1 = A.y; b2 = A.z; b3 = A.w; b4 = B.x; break;
                    case 1:  b0 = A.y; b1 = A.z; b2 = A.w; b3 = B.x; b4 = B.y; break;
                    case 2:  b0 = A.z; b1 = A.w; b2 = B.x; b3 = B.y; b4 = B.z; break;
                    default: b0 = A.w; b1 = B.x; b2 = B.y; b3 = B.z; b4 = B.w; break;
                }
                res.x = wx0 * b0 + fx * b1;
                res.y = wx0 * b1 + fx * b2;
                res.z = wx0 * b2 + fx * b3;
                res.w = wx0 * b3 + fx * b4;
            } else {
                const float* sf = (const float*)S;
                float r[4];
#pragma unroll
                for (int jj = 0; jj < 4; jj++) {
                    const int x0  = 4 * j + sx + jj;
                    const int xm0 = mirror_idx(x0,     IMG_W);
                    const int xm1 = mirror_idx(x0 + 1, IMG_W);
                    r[jj] = wx0 * sf[xm0] + fx * sf[xm1];
                }
                res.x = r[0]; res.y = r[1]; res.z = r[2]; res.w = r[3];
            }
            orow[j] = res;
        }

#pragma unroll
        for (int c = 0; c < 4; c++) { rA[c] = rB[c]; rB[c] = rC[c]; }
    }
}

extern "C" void kernel_launch(void* const* d_in, const int* in_sizes, int n_in,
                              void* d_out, int out_size) {
    const float* images = (const float*)d_in[0];  // (256, 512, 512, 1) f32
    const float* dxdy   = (const float*)d_in[1];  // (256, 2) f32
    float* out = (float*)d_out;                   // (256, 512, 512) f32

    dim3 grid(IMG_H / ROWS_PER_CTA, N_IMG);       // (8, 256)
    dim3 block(WARPS * 32);
    shift_bilinear_kernel<<<grid, block>>>(images, dxdy, out);
}